// round 2
// baseline (speedup 1.0000x reference)
#include <cuda_runtime.h>
#include <math.h>

#define N_MAX   196608
#define TILE    96
#define TMAX    2048
#define MAXDET  100
#define NBINS   8192
#define BSHIFT  10
#define TARGETK 1024
#define CAP     1536
#define LOU     0xBC23D70Au   // ordf(0.01f)

__device__ float              g_scores[N_MAX];
__device__ float4             g_boxes[N_MAX];
__device__ int                g_hist[NBINS];
__device__ int                g_binStart[NBINS];
__device__ unsigned long long g_candKey[CAP];
__device__ int                g_tau;
__device__ int                g_total;

__device__ __forceinline__ unsigned ordf(float f) {
    unsigned u = __float_as_uint(f);
    return (u & 0x80000000u) ? ~u : (u | 0x80000000u);
}
__device__ __forceinline__ float unordf(unsigned u) {
    return __uint_as_float((u & 0x80000000u) ? (u ^ 0x80000000u) : ~u);
}
__device__ __forceinline__ float read_dim(const void* p) {
    int iv = *(const int*)p;
    if (iv >= 1 && iv <= (1 << 20)) return (float)iv;
    float fv = *(const float*)p;
    if (fv >= 1.0f && fv <= 1048576.0f) return fv;
    double dv = *(const double*)p;
    if (dv >= 1.0 && dv <= 1048576.0) return (float)dv;
    long long lv = *(const long long*)p;
    return (float)lv;
}
__device__ __forceinline__ bool iou_gt_half(float4 A, float4 B) {
    float x1 = fmaxf(A.x, B.x), y1 = fmaxf(A.y, B.y);
    float x2 = fminf(A.z, B.z), y2 = fminf(A.w, B.w);
    float inter = fmaxf(x2 - x1, 0.0f) * fmaxf(y2 - y1, 0.0f);
    float a1 = (A.z - A.x) * (A.w - A.y);
    float a2 = (B.z - B.x) * (B.w - B.y);
    float iou = inter / (a1 + a2 - inter + 1e-8f);
    return iou > 0.5f;
}

// ---------------------------------------------------------------------------
// Kernel 1: decode. Block handles 64 anchors; 90-class rows staged through
// smem with coalesced float4 loads; 4 threads per anchor compute class max.
// Also builds the score-bit histogram for the top-K bucket sort.
// ---------------------------------------------------------------------------
__global__ void decode_kernel(const float* __restrict__ cls,
                              const float* __restrict__ reg,
                              const float* __restrict__ anc,
                              const void* ph, const void* pw,
                              int N, int C) {
    __shared__ float sCls[64 * 90];
    int a0  = blockIdx.x * 64;
    int tid = threadIdx.x;
    int nA  = min(64, N - a0);
    if (nA <= 0) return;
    int totalF = nA * C;
    long long base = (long long)a0 * C;

    const float4* src = (const float4*)(cls + base);
    int nF4 = totalF >> 2;
    for (int k = tid; k < nF4; k += 256) ((float4*)sCls)[k] = src[k];
    for (int k = (nF4 << 2) + tid; k < totalF; k += 256) sCls[k] = cls[base + k];
    __syncthreads();

    int g = tid >> 2, sub = tid & 3;
    int i = a0 + g;
    float m = -INFINITY;
    if (g < nA)
        for (int k = sub; k < C; k += 4) m = fmaxf(m, sCls[g * C + k]);
    unsigned u = ordf(m);
    u = max(u, __shfl_xor_sync(0xffffffffu, u, 1));
    u = max(u, __shfl_xor_sync(0xffffffffu, u, 2));

    if (sub == 0 && g < nA) {
        float best = unordf(u);
        float imw = read_dim(pw);
        float imh = read_dim(ph);
        float4 a = ((const float4*)anc)[i];
        float4 r = ((const float4*)reg)[i];
        float wa  = a.z - a.x;
        float ha  = a.w - a.y;
        float cxa = a.x + 0.5f * wa;
        float cya = a.y + 0.5f * ha;
        float cx  = cxa + r.x * 0.1f * wa;
        float cy  = cya + r.y * 0.1f * ha;
        float w   = expf(r.z * 0.2f) * wa;
        float h   = expf(r.w * 0.2f) * ha;
        float4 b;
        b.x = fminf(fmaxf(cx - 0.5f * w, 0.0f), imw);
        b.y = fminf(fmaxf(cy - 0.5f * h, 0.0f), imh);
        b.z = fminf(fmaxf(cx + 0.5f * w, 0.0f), imw);
        b.w = fminf(fmaxf(cy + 0.5f * h, 0.0f), imh);
        g_boxes[i] = b;
        bool pass = best > 0.01f;
        g_scores[i] = pass ? best : -INFINITY;
        if (pass) {
            unsigned bu = ordf(best);
            int bin = min((int)((bu - LOU) >> BSHIFT), NBINS - 1);
            atomicAdd(&g_hist[bin], 1);
        }
    }
}

// ---------------------------------------------------------------------------
// Kernel 2: single block. From the histogram pick threshold bin tau such that
// #candidates in bins >= tau is ~TARGETK; write descending-order bin starts.
// ---------------------------------------------------------------------------
__global__ void findtau_kernel() {
    __shared__ int cSum[256];
    int tid = threadIdx.x;
    int c0 = tid * (NBINS / 256);
    int local[NBINS / 256];
    int s = 0;
    #pragma unroll
    for (int k = 0; k < NBINS / 256; k++) { local[k] = g_hist[c0 + k]; s += local[k]; }
    cSum[tid] = s;
    __syncthreads();
    int suffix = 0;
    for (int t = tid + 1; t < 256; t++) suffix += cSum[t];

    if (suffix < TARGETK && suffix + s >= TARGETK) {
        int run = suffix;
        for (int k = NBINS / 256 - 1; k >= 0; k--) {
            run += local[k];
            if (run >= TARGETK) { g_tau = c0 + k; g_total = run; break; }
        }
    }
    if (tid == 0 && suffix + s < TARGETK) { g_tau = 0; g_total = suffix + s; }

    int run2 = suffix;
    for (int k = NBINS / 256 - 1; k >= 0; k--) {
        g_binStart[c0 + k] = run2;
        run2 += local[k];
    }
}

// ---------------------------------------------------------------------------
// Kernel 3: compact candidates with bin >= tau into g_candKey at bin-ordered
// positions (descending score order up to intra-bin permutation).
// Also zeroes the histogram for the next graph replay.
// ---------------------------------------------------------------------------
__global__ void compact_kernel(int N) {
    int gid = blockIdx.x * blockDim.x + threadIdx.x;
    if (gid < NBINS) g_hist[gid] = 0;
    if (gid >= N) return;
    float sc = g_scores[gid];
    unsigned u = ordf(sc);
    if (u > LOU) {
        int bin = min((int)((u - LOU) >> BSHIFT), NBINS - 1);
        if (bin >= g_tau) {
            int pos = atomicAdd(&g_binStart[bin], 1);
            if (pos < CAP)
                g_candKey[pos] = ((unsigned long long)u << 32) | (unsigned)(~gid);
        }
    }
}

// ---------------------------------------------------------------------------
// Kernel 4: single block. Odd-even cleanup sort of candidates (nearly sorted),
// warp-batched greedy NMS (exact reference order), class argmax for selected,
// output. Fallback pop-loop path guarantees correctness if top-K exhausts.
// ---------------------------------------------------------------------------
__global__ void nms_kernel(float* __restrict__ out,
                           const float* __restrict__ cls,
                           int N, int C) {
    __shared__ unsigned long long sKeys[TMAX];
    __shared__ float4 sSelBox[MAXDET];
    __shared__ int    sSelIdx[MAXDET];
    __shared__ float  sSelScore[MAXDET];
    __shared__ int    sNsel, sFlag, sSup;
    __shared__ float4 sBx;
    __shared__ unsigned long long sWarp[8];
    __shared__ unsigned long long sTileP[3];

    int tid  = threadIdx.x;
    int wid  = tid >> 5;
    int lane = tid & 31;
    const unsigned FULL = 0xffffffffu;

    int total = g_total;
    int tau   = g_tau;
    bool ovf  = total > CAP;
    int cnt   = ovf ? 0 : total;

    if (tid == 0) sNsel = 0;
    for (int k = tid; k < cnt; k += 256) sKeys[k] = g_candKey[k];
    __syncthreads();

    // ---- odd-even transposition cleanup (descending) ----
    if (cnt > 1) {
        for (;;) {
            if (tid == 0) sFlag = 0;
            __syncthreads();
            for (int i = 2 * tid; i + 1 < cnt; i += 512) {
                unsigned long long a = sKeys[i], b = sKeys[i + 1];
                if (b > a) { sKeys[i] = b; sKeys[i + 1] = a; sFlag = 1; }
            }
            __syncthreads();
            for (int i = 2 * tid + 1; i + 1 < cnt; i += 512) {
                unsigned long long a = sKeys[i], b = sKeys[i + 1];
                if (b > a) { sKeys[i] = b; sKeys[i + 1] = a; sFlag = 1; }
            }
            __syncthreads();
            if (!sFlag) break;
            __syncthreads();
        }
    }

    // ---- warp-batched greedy NMS over sorted candidates (warp 0) ----
    if (tid < 32) {
        int nsel = 0;
        for (int bse = 0; bse < cnt && nsel < MAXDET; bse += 32) {
            __syncwarp();
            int p = bse + tid;
            bool alive = p < cnt;
            unsigned long long key = alive ? sKeys[p] : 0ull;
            unsigned hi = (unsigned)(key >> 32);
            int   idx = (int)(~(unsigned)(key & 0xffffffffu));
            float sc  = unordf(hi);
            alive = alive && hi > 0x007FFFFFu;
            float4 b = make_float4(0.f, 0.f, 0.f, 0.f);
            if (alive) b = g_boxes[idx];
            for (int j = 0; j < nsel; j++)
                if (alive && iou_gt_half(b, sSelBox[j])) alive = false;
            unsigned am = __ballot_sync(FULL, alive);
            while (am && nsel < MAXDET) {
                int l = __ffs(am) - 1;
                float4 sb;
                sb.x = __shfl_sync(FULL, b.x, l);
                sb.y = __shfl_sync(FULL, b.y, l);
                sb.z = __shfl_sync(FULL, b.z, l);
                sb.w = __shfl_sync(FULL, b.w, l);
                if (tid == l) { sSelBox[nsel] = b; sSelIdx[nsel] = idx; sSelScore[nsel] = sc; }
                if (alive && tid > l && iou_gt_half(b, sb)) alive = false;
                nsel++;
                am = __ballot_sync(FULL, alive) & (0xFFFFFFFEu << l);
            }
        }
        if (tid == 0) sNsel = nsel;
    }
    __syncthreads();
    int nsel = sNsel;

    // ---- fallback: continue exactly if top-K exhausted or bucket overflow ----
    if (nsel < MAXDET && (ovf || tau > 0)) {
        unsigned tauOrd = ovf ? 0xFFFFFFFFu : (LOU + ((unsigned)tau << BSHIFT));
        int T = (N + TILE - 1) / TILE;
        for (int t = tid; t < TMAX; t += 256) {
            unsigned long long best = 0ull;
            if (t < T) {
                int bb = t * TILE;
                for (int k = 0; k < TILE; k++) {
                    int ii = bb + k;
                    if (ii >= N) break;
                    unsigned u = ordf(g_scores[ii]);
                    if (u >= tauOrd) continue;  // consumed in phase 1
                    unsigned long long kk =
                        ((unsigned long long)u << 32) | (unsigned)(~ii);
                    if (kk > best) best = kk;
                }
            }
            sKeys[t] = best;
        }
        __syncthreads();

        while (nsel < MAXDET) {
            unsigned long long best = 0ull;
            #pragma unroll
            for (int k = 0; k < TMAX / 256; k++) {
                unsigned long long v = sKeys[tid + k * 256];
                best = (v > best) ? v : best;
            }
            #pragma unroll
            for (int off = 16; off; off >>= 1) {
                unsigned long long o = __shfl_down_sync(FULL, best, off);
                best = (o > best) ? o : best;
            }
            if (lane == 0) sWarp[wid] = best;
            __syncthreads();
            if (tid < 32) {
                unsigned long long v = (tid < 8) ? sWarp[tid] : 0ull;
                #pragma unroll
                for (int off = 4; off; off >>= 1) {
                    unsigned long long o = __shfl_down_sync(FULL, v, off);
                    v = (o > v) ? o : v;
                }
                if (tid == 0) sWarp[0] = v;
            }
            __syncthreads();
            unsigned long long win = sWarp[0];
            unsigned hi = (unsigned)(win >> 32);
            if (hi <= 0x007FFFFFu) break;
            int   i   = (int)(~(unsigned)(win & 0xffffffffu));
            float val = unordf(hi);
            if (tid == 0) { g_scores[i] = -INFINITY; sBx = g_boxes[i]; sSup = 0; }
            __syncthreads();
            int t = i / TILE;
            if (tid < TILE) {
                int ii = t * TILE + tid;
                unsigned u = (ii < N) ? ordf(g_scores[ii]) : 0x007FFFFFu;
                unsigned long long kk = 0ull;
                if (u < tauOrd)
                    kk = ((unsigned long long)u << 32) | (unsigned)(~ii);
                #pragma unroll
                for (int off = 16; off; off >>= 1) {
                    unsigned long long o = __shfl_down_sync(FULL, kk, off);
                    kk = (o > kk) ? o : kk;
                }
                if (lane == 0) sTileP[wid] = kk;
            }
            if (tid >= 128 && tid < 128 + nsel) {
                if (iou_gt_half(sSelBox[tid - 128], sBx)) sSup = 1;
            }
            __syncthreads();
            if (tid == 0) {
                unsigned long long kk = sTileP[0];
                if (sTileP[1] > kk) kk = sTileP[1];
                if (sTileP[2] > kk) kk = sTileP[2];
                sKeys[t] = kk;
                if (!sSup) {
                    sSelBox[nsel] = sBx; sSelIdx[nsel] = i; sSelScore[nsel] = val;
                    sNsel = nsel + 1;
                }
            }
            __syncthreads();
            nsel = sNsel;
        }
    }
    __syncthreads();
    nsel = sNsel;

    // ---- class argmax for selected rows (warp per row) ----
    for (int r = wid; r < nsel; r += 8) {
        int i = sSelIdx[r];
        const float* row = cls + (long long)i * C;
        float best = -INFINITY;
        int   bidx = 0x7fffffff;
        for (int j = lane; j < C; j += 32) {
            float v = row[j];
            if (v > best) { best = v; bidx = j; }
        }
        #pragma unroll
        for (int off = 16; off; off >>= 1) {
            float ov = __shfl_down_sync(FULL, best, off);
            int   oi = __shfl_down_sync(FULL, bidx, off);
            if (ov > best || (ov == best && oi < bidx)) { best = ov; bidx = oi; }
        }
        if (lane == 0) out[100 + r] = (float)bidx;
    }

    // ---- scores, boxes, keep + defaults ----
    for (int r = tid; r < MAXDET; r += 256) {
        bool k = r < nsel;
        out[r]       = k ? sSelScore[r] : 0.0f;
        out[600 + r] = k ? 1.0f : 0.0f;
        float4 b = k ? sSelBox[r] : make_float4(0.f, 0.f, 0.f, 0.f);
        out[200 + 4 * r + 0] = b.x;
        out[200 + 4 * r + 1] = b.y;
        out[200 + 4 * r + 2] = b.z;
        out[200 + 4 * r + 3] = b.w;
        if (!k) out[100 + r] = -1.0f;
    }
}

extern "C" void kernel_launch(void* const* d_in, const int* in_sizes, int n_in,
                              void* d_out, int out_size) {
    const float* cls = (const float*)d_in[0];
    const float* reg = (const float*)d_in[1];
    const float* anc = (const float*)d_in[2];
    const void*  ph  = d_in[3];
    const void*  pw  = d_in[4];

    int N = in_sizes[2] / 4;
    int C = in_sizes[0] / N;

    int blocksD = (N + 63) / 64;
    decode_kernel<<<blocksD, 256>>>(cls, reg, anc, ph, pw, N, C);

    findtau_kernel<<<1, 256>>>();

    int blocksC = (N + 255) / 256;
    compact_kernel<<<blocksC, 256>>>(N);

    nms_kernel<<<1, 256>>>((float*)d_out, cls, N, C);
}

// round 3
// speedup vs baseline: 1.9055x; 1.9055x over previous
#include <cuda_runtime.h>
#include <math.h>

#define N_MAX   196608
#define TILE    96
#define TMAX    2048
#define MAXDET  100
#define NBINS   32768
#define BSHIFT  8
#define TARGETK 512
#define CAP     2048
#define LOU     0xBC23D70Au   // ordf(0.01f)
#define NMS_T   512

__device__ float              g_scores[N_MAX];
__device__ float4             g_boxes[N_MAX];
__device__ int                g_hist[NBINS];
__device__ int                g_binStart[NBINS];
__device__ unsigned long long g_candKey[CAP];
__device__ int                g_tau;
__device__ int                g_total;

__device__ __forceinline__ unsigned ordf(float f) {
    unsigned u = __float_as_uint(f);
    return (u & 0x80000000u) ? ~u : (u | 0x80000000u);
}
__device__ __forceinline__ float unordf(unsigned u) {
    return __uint_as_float((u & 0x80000000u) ? (u ^ 0x80000000u) : ~u);
}
__device__ __forceinline__ float read_dim(const void* p) {
    int iv = *(const int*)p;
    if (iv >= 1 && iv <= (1 << 20)) return (float)iv;
    float fv = *(const float*)p;
    if (fv >= 1.0f && fv <= 1048576.0f) return fv;
    double dv = *(const double*)p;
    if (dv >= 1.0 && dv <= 1048576.0) return (float)dv;
    long long lv = *(const long long*)p;
    return (float)lv;
}
__device__ __forceinline__ bool iou_gt_half(float4 A, float4 B) {
    float x1 = fmaxf(A.x, B.x), y1 = fmaxf(A.y, B.y);
    float x2 = fminf(A.z, B.z), y2 = fminf(A.w, B.w);
    float inter = fmaxf(x2 - x1, 0.0f) * fmaxf(y2 - y1, 0.0f);
    float a1 = (A.z - A.x) * (A.w - A.y);
    float a2 = (B.z - B.x) * (B.w - B.y);
    float iou = inter / (a1 + a2 - inter + 1e-8f);
    return iou > 0.5f;
}

// ---------------------------------------------------------------------------
// Kernel 1: decode. 64 anchors/block, 90-class rows staged via coalesced
// float4 into smem, 4 threads/anchor class max, box decode, histogram.
// ---------------------------------------------------------------------------
__global__ void decode_kernel(const float* __restrict__ cls,
                              const float* __restrict__ reg,
                              const float* __restrict__ anc,
                              const void* ph, const void* pw,
                              int N, int C) {
    __shared__ float sCls[64 * 90];
    int a0  = blockIdx.x * 64;
    int tid = threadIdx.x;
    int nA  = min(64, N - a0);
    if (nA <= 0) return;
    int totalF = nA * C;
    long long base = (long long)a0 * C;

    const float4* src = (const float4*)(cls + base);
    int nF4 = totalF >> 2;
    for (int k = tid; k < nF4; k += 256) ((float4*)sCls)[k] = src[k];
    for (int k = (nF4 << 2) + tid; k < totalF; k += 256) sCls[k] = cls[base + k];
    __syncthreads();

    int g = tid >> 2, sub = tid & 3;
    int i = a0 + g;
    float m = -INFINITY;
    if (g < nA)
        for (int k = sub; k < C; k += 4) m = fmaxf(m, sCls[g * C + k]);
    unsigned u = ordf(m);
    u = max(u, __shfl_xor_sync(0xffffffffu, u, 1));
    u = max(u, __shfl_xor_sync(0xffffffffu, u, 2));

    if (sub == 0 && g < nA) {
        float best = unordf(u);
        float imw = read_dim(pw);
        float imh = read_dim(ph);
        float4 a = ((const float4*)anc)[i];
        float4 r = ((const float4*)reg)[i];
        float wa  = a.z - a.x;
        float ha  = a.w - a.y;
        float cxa = a.x + 0.5f * wa;
        float cya = a.y + 0.5f * ha;
        float cx  = cxa + r.x * 0.1f * wa;
        float cy  = cya + r.y * 0.1f * ha;
        float w   = expf(r.z * 0.2f) * wa;
        float h   = expf(r.w * 0.2f) * ha;
        float4 b;
        b.x = fminf(fmaxf(cx - 0.5f * w, 0.0f), imw);
        b.y = fminf(fmaxf(cy - 0.5f * h, 0.0f), imh);
        b.z = fminf(fmaxf(cx + 0.5f * w, 0.0f), imw);
        b.w = fminf(fmaxf(cy + 0.5f * h, 0.0f), imh);
        g_boxes[i] = b;
        bool pass = best > 0.01f;
        g_scores[i] = pass ? best : -INFINITY;
        if (pass) {
            int bin = min((int)((u - LOU) >> BSHIFT), NBINS - 1);
            atomicAdd(&g_hist[bin], 1);
        }
    }
}

// ---------------------------------------------------------------------------
// Kernel 2: single block, 1024 threads, 32 bins/thread. Suffix sums via
// warp shuffles; pick tau so that count(bins >= tau) >= TARGETK; write
// descending-order bin start offsets.
// ---------------------------------------------------------------------------
__global__ void findtau_kernel() {
    __shared__ int sWarpSum[32];
    const unsigned FULL = 0xffffffffu;
    int tid  = threadIdx.x;
    int lane = tid & 31;
    int wid  = tid >> 5;
    int c0 = tid * (NBINS / 1024);
    int local[NBINS / 1024];
    int s = 0;
    #pragma unroll
    for (int k = 0; k < NBINS / 1024; k++) { local[k] = g_hist[c0 + k]; s += local[k]; }

    // inclusive suffix within warp
    int suf = s;
    #pragma unroll
    for (int off = 1; off < 32; off <<= 1) {
        int v = __shfl_down_sync(FULL, suf, off);
        if (lane + off < 32) suf += v;
    }
    if (lane == 0) sWarpSum[wid] = suf;   // warp total
    __syncthreads();
    int hiSum = 0;
    for (int w = wid + 1; w < 32; w++) hiSum += sWarpSum[w];
    int suffix = hiSum + (suf - s);       // strictly after tid

    if (suffix < TARGETK && suffix + s >= TARGETK) {
        int run = suffix;
        for (int k = NBINS / 1024 - 1; k >= 0; k--) {
            run += local[k];
            if (run >= TARGETK) { g_tau = c0 + k; g_total = run; break; }
        }
    }
    if (tid == 0 && suffix + s < TARGETK) { g_tau = 0; g_total = suffix + s; }

    int run2 = suffix;
    #pragma unroll
    for (int k = NBINS / 1024 - 1; k >= 0; k--) {
        g_binStart[c0 + k] = run2;
        run2 += local[k];
    }
}

// ---------------------------------------------------------------------------
// Kernel 3: compact candidates in bins >= tau; zero histogram for next replay.
// ---------------------------------------------------------------------------
__global__ void compact_kernel(int N) {
    int gid = blockIdx.x * blockDim.x + threadIdx.x;
    if (gid < NBINS) g_hist[gid] = 0;
    if (gid >= N) return;
    unsigned u = ordf(g_scores[gid]);
    if (u > LOU) {
        int bin = min((int)((u - LOU) >> BSHIFT), NBINS - 1);
        if (bin >= g_tau) {
            int pos = atomicAdd(&g_binStart[bin], 1);
            if (pos < CAP)
                g_candKey[pos] = ((unsigned long long)u << 32) | (unsigned)(~gid);
        }
    }
}

// ---------------------------------------------------------------------------
// Kernel 4: single block, 512 threads. Bitonic sort (desc) of candidates,
// warp-batched greedy NMS (exact reference order), class argmax of winners.
// Fallback pop-loop guarantees exactness on any distribution.
// ---------------------------------------------------------------------------
__global__ void nms_kernel(float* __restrict__ out,
                           const float* __restrict__ cls,
                           int N, int C) {
    __shared__ unsigned long long sKeys[TMAX];
    __shared__ float4 sSelBox[MAXDET];
    __shared__ int    sSelIdx[MAXDET];
    __shared__ float  sSelScore[MAXDET];
    __shared__ int    sNsel, sSup;
    __shared__ float4 sBx;
    __shared__ unsigned long long sWarp[16];
    __shared__ unsigned long long sTileP[3];

    int tid  = threadIdx.x;
    int wid  = tid >> 5;
    int lane = tid & 31;
    const unsigned FULL = 0xffffffffu;

    int total = g_total;
    int tau   = g_tau;
    bool ovf  = total > CAP;
    int cnt   = ovf ? 0 : total;

    if (tid == 0) sNsel = 0;

    // pow2 size for bitonic
    int M = 1; while (M < cnt) M <<= 1;
    if (M < 2) M = 2;

    for (int k = tid; k < M; k += NMS_T)
        sKeys[k] = (k < cnt) ? g_candKey[k] : 0ull;
    __syncthreads();

    // ---- bitonic sort, descending ----
    if (cnt > 1) {
        for (int k2 = 2; k2 <= M; k2 <<= 1) {
            for (int j = k2 >> 1; j > 0; j >>= 1) {
                for (int i = tid; i < M; i += NMS_T) {
                    int l = i ^ j;
                    if (l > i) {
                        unsigned long long a = sKeys[i], b = sKeys[l];
                        bool desc = ((i & k2) == 0);
                        if (desc ? (a < b) : (a > b)) { sKeys[i] = b; sKeys[l] = a; }
                    }
                }
                __syncthreads();
            }
        }
    }

    // ---- warp-batched greedy NMS over sorted candidates (warp 0) ----
    if (tid < 32) {
        int nsel = 0;
        for (int bse = 0; bse < cnt && nsel < MAXDET; bse += 32) {
            __syncwarp();
            int p = bse + tid;
            bool alive = p < cnt;
            unsigned long long key = alive ? sKeys[p] : 0ull;
            unsigned hi = (unsigned)(key >> 32);
            int   idx = (int)(~(unsigned)(key & 0xffffffffu));
            float sc  = unordf(hi);
            alive = alive && hi > 0x007FFFFFu;
            float4 b = make_float4(0.f, 0.f, 0.f, 0.f);
            if (alive) b = g_boxes[idx];
            for (int j = 0; j < nsel; j++)
                if (alive && iou_gt_half(b, sSelBox[j])) alive = false;
            unsigned am = __ballot_sync(FULL, alive);
            while (am && nsel < MAXDET) {
                int l = __ffs(am) - 1;
                float4 sb;
                sb.x = __shfl_sync(FULL, b.x, l);
                sb.y = __shfl_sync(FULL, b.y, l);
                sb.z = __shfl_sync(FULL, b.z, l);
                sb.w = __shfl_sync(FULL, b.w, l);
                if (tid == l) { sSelBox[nsel] = b; sSelIdx[nsel] = idx; sSelScore[nsel] = sc; }
                if (alive && tid > l && iou_gt_half(b, sb)) alive = false;
                nsel++;
                am = __ballot_sync(FULL, alive) & (0xFFFFFFFEu << l);
            }
        }
        if (tid == 0) sNsel = nsel;
    }
    __syncthreads();
    int nsel = sNsel;

    // ---- fallback (exactness guarantee; not expected to run) ----
    if (nsel < MAXDET && (ovf || tau > 0)) {
        unsigned tauOrd = ovf ? 0xFFFFFFFFu : (LOU + ((unsigned)tau << BSHIFT));
        int T = (N + TILE - 1) / TILE;
        for (int t = tid; t < TMAX; t += NMS_T) {
            unsigned long long best = 0ull;
            if (t < T) {
                int bb = t * TILE;
                for (int k = 0; k < TILE; k++) {
                    int ii = bb + k;
                    if (ii >= N) break;
                    unsigned u = ordf(g_scores[ii]);
                    if (u >= tauOrd) continue;  // consumed in phase 1
                    unsigned long long kk =
                        ((unsigned long long)u << 32) | (unsigned)(~ii);
                    if (kk > best) best = kk;
                }
            }
            sKeys[t] = best;
        }
        __syncthreads();

        while (nsel < MAXDET) {
            unsigned long long best = 0ull;
            #pragma unroll
            for (int k = 0; k < TMAX / NMS_T; k++) {
                unsigned long long v = sKeys[tid + k * NMS_T];
                best = (v > best) ? v : best;
            }
            #pragma unroll
            for (int off = 16; off; off >>= 1) {
                unsigned long long o = __shfl_down_sync(FULL, best, off);
                best = (o > best) ? o : best;
            }
            if (lane == 0) sWarp[wid] = best;
            __syncthreads();
            if (tid < 32) {
                unsigned long long v = (tid < 16) ? sWarp[tid] : 0ull;
                #pragma unroll
                for (int off = 8; off; off >>= 1) {
                    unsigned long long o = __shfl_down_sync(FULL, v, off);
                    v = (o > v) ? o : v;
                }
                if (tid == 0) sWarp[0] = v;
            }
            __syncthreads();
            unsigned long long win = sWarp[0];
            unsigned hi = (unsigned)(win >> 32);
            if (hi <= 0x007FFFFFu) break;
            int   i   = (int)(~(unsigned)(win & 0xffffffffu));
            float val = unordf(hi);
            if (tid == 0) { g_scores[i] = -INFINITY; sBx = g_boxes[i]; sSup = 0; }
            __syncthreads();
            int t = i / TILE;
            if (tid < TILE) {
                int ii = t * TILE + tid;
                unsigned u = (ii < N) ? ordf(g_scores[ii]) : 0x007FFFFFu;
                unsigned long long kk = 0ull;
                if (u < tauOrd)
                    kk = ((unsigned long long)u << 32) | (unsigned)(~ii);
                #pragma unroll
                for (int off = 16; off; off >>= 1) {
                    unsigned long long o = __shfl_down_sync(FULL, kk, off);
                    kk = (o > kk) ? o : kk;
                }
                if (lane == 0) sTileP[wid] = kk;
            }
            if (tid >= 128 && tid < 128 + nsel) {
                if (iou_gt_half(sSelBox[tid - 128], sBx)) sSup = 1;
            }
            __syncthreads();
            if (tid == 0) {
                unsigned long long kk = sTileP[0];
                if (sTileP[1] > kk) kk = sTileP[1];
                if (sTileP[2] > kk) kk = sTileP[2];
                sKeys[t] = kk;
                if (!sSup) {
                    sSelBox[nsel] = sBx; sSelIdx[nsel] = i; sSelScore[nsel] = val;
                    sNsel = nsel + 1;
                }
            }
            __syncthreads();
            nsel = sNsel;
        }
    }
    __syncthreads();
    nsel = sNsel;

    // ---- class argmax for selected rows (warp per row) ----
    for (int r = wid; r < nsel; r += NMS_T / 32) {
        int i = sSelIdx[r];
        const float* row = cls + (long long)i * C;
        float best = -INFINITY;
        int   bidx = 0x7fffffff;
        for (int j = lane; j < C; j += 32) {
            float v = row[j];
            if (v > best) { best = v; bidx = j; }
        }
        #pragma unroll
        for (int off = 16; off; off >>= 1) {
            float ov = __shfl_down_sync(FULL, best, off);
            int   oi = __shfl_down_sync(FULL, bidx, off);
            if (ov > best || (ov == best && oi < bidx)) { best = ov; bidx = oi; }
        }
        if (lane == 0) out[100 + r] = (float)bidx;
    }

    // ---- scores, boxes, keep + defaults ----
    for (int r = tid; r < MAXDET; r += NMS_T) {
        bool k = r < nsel;
        out[r]       = k ? sSelScore[r] : 0.0f;
        out[600 + r] = k ? 1.0f : 0.0f;
        float4 b = k ? sSelBox[r] : make_float4(0.f, 0.f, 0.f, 0.f);
        out[200 + 4 * r + 0] = b.x;
        out[200 + 4 * r + 1] = b.y;
        out[200 + 4 * r + 2] = b.z;
        out[200 + 4 * r + 3] = b.w;
        if (!k) out[100 + r] = -1.0f;
    }
}

extern "C" void kernel_launch(void* const* d_in, const int* in_sizes, int n_in,
                              void* d_out, int out_size) {
    const float* cls = (const float*)d_in[0];
    const float* reg = (const float*)d_in[1];
    const float* anc = (const float*)d_in[2];
    const void*  ph  = d_in[3];
    const void*  pw  = d_in[4];

    int N = in_sizes[2] / 4;
    int C = in_sizes[0] / N;

    int blocksD = (N + 63) / 64;
    decode_kernel<<<blocksD, 256>>>(cls, reg, anc, ph, pw, N, C);

    findtau_kernel<<<1, 1024>>>();

    int blocksC = (N + 255) / 256;
    compact_kernel<<<blocksC, 256>>>(N);

    nms_kernel<<<1, NMS_T>>>((float*)d_out, cls, N, C);
}

// round 4
// speedup vs baseline: 2.8579x; 1.4998x over previous
#include <cuda_runtime.h>
#include <math.h>

#define N_MAX   196608
#define TILE    96
#define TMAX    2048
#define MAXDET  100
#define WBINS   1024
#define WSHIFT  4
#define TARGETK 192
#define CAP     2048
#define LOU     0xBC23D70Au   // ordf(0.01f)
#define NMS_T   512

__device__ float              g_scores[N_MAX];
__device__ float4             g_boxes[N_MAX];
__device__ unsigned           g_maxu;          // zero-init; reset by nms each replay
__device__ int                g_hist[WBINS];
__device__ int                g_binStart[WBINS];
__device__ unsigned long long g_candKey[CAP];
__device__ int                g_total;
__device__ unsigned           g_cutU;

__device__ __forceinline__ unsigned ordf(float f) {
    unsigned u = __float_as_uint(f);
    return (u & 0x80000000u) ? ~u : (u | 0x80000000u);
}
__device__ __forceinline__ float unordf(unsigned u) {
    return __uint_as_float((u & 0x80000000u) ? (u ^ 0x80000000u) : ~u);
}
__device__ __forceinline__ float read_dim(const void* p) {
    int iv = *(const int*)p;
    if (iv >= 1 && iv <= (1 << 20)) return (float)iv;
    float fv = *(const float*)p;
    if (fv >= 1.0f && fv <= 1048576.0f) return fv;
    double dv = *(const double*)p;
    if (dv >= 1.0 && dv <= 1048576.0) return (float)dv;
    long long lv = *(const long long*)p;
    return (float)lv;
}
__device__ __forceinline__ bool iou_gt_half(float4 A, float4 B) {
    float x1 = fmaxf(A.x, B.x), y1 = fmaxf(A.y, B.y);
    float x2 = fminf(A.z, B.z), y2 = fminf(A.w, B.w);
    float inter = fmaxf(x2 - x1, 0.0f) * fmaxf(y2 - y1, 0.0f);
    float a1 = (A.z - A.x) * (A.w - A.y);
    float a2 = (B.z - B.x) * (B.w - B.y);
    float iou = inter / (a1 + a2 - inter + 1e-8f);
    return iou > 0.5f;
}

// ---------------------------------------------------------------------------
// Kernel 1: decode. 64 anchors/block. Coalesced float4 stream over the class
// rows; register max of 4 + one smem atomicMax per float4 (split at the one
// 2-anchor boundary float4 per 45). Epilogue: 64 threads decode boxes,
// threshold, and block-reduce the max ordered score into g_maxu.
// ---------------------------------------------------------------------------
__global__ void decode_kernel(const float* __restrict__ cls,
                              const float* __restrict__ reg,
                              const float* __restrict__ anc,
                              const void* ph, const void* pw,
                              int N, int C) {
    __shared__ unsigned sMax[64];
    int a0  = blockIdx.x * 64;
    int tid = threadIdx.x;
    int nA  = min(64, N - a0);
    if (nA <= 0) return;
    if (tid < 64) sMax[tid] = 0u;
    __syncthreads();

    if (nA == 64 && C == 90) {
        const float4* src = (const float4*)(cls + (long long)a0 * 90);
        #pragma unroll 2
        for (int k = tid; k < 1440; k += 256) {
            float4 v = src[k];
            int f = k * 4;
            int a = f / 90;
            int r = f - a * 90;
            if (r <= 86) {
                float m = fmaxf(fmaxf(v.x, v.y), fmaxf(v.z, v.w));
                atomicMax(&sMax[a], ordf(m));
            } else {   // r == 88: x,y -> anchor a; z,w -> anchor a+1
                atomicMax(&sMax[a],     ordf(fmaxf(v.x, v.y)));
                atomicMax(&sMax[a + 1], ordf(fmaxf(v.z, v.w)));
            }
        }
    } else {
        long long base = (long long)a0 * C;
        int totalF = nA * C;
        for (int k = tid; k < totalF; k += 256)
            atomicMax(&sMax[k / C], ordf(cls[base + k]));
    }
    __syncthreads();

    unsigned u = 0u;
    if (tid < nA) {
        u = sMax[tid];
        int i = a0 + tid;
        float best = unordf(u);
        float imw = read_dim(pw);
        float imh = read_dim(ph);
        float4 a = ((const float4*)anc)[i];
        float4 r = ((const float4*)reg)[i];
        float wa  = a.z - a.x;
        float ha  = a.w - a.y;
        float cxa = a.x + 0.5f * wa;
        float cya = a.y + 0.5f * ha;
        float cx  = cxa + r.x * 0.1f * wa;
        float cy  = cya + r.y * 0.1f * ha;
        float w   = expf(r.z * 0.2f) * wa;
        float h   = expf(r.w * 0.2f) * ha;
        float4 b;
        b.x = fminf(fmaxf(cx - 0.5f * w, 0.0f), imw);
        b.y = fminf(fmaxf(cy - 0.5f * h, 0.0f), imh);
        b.z = fminf(fmaxf(cx + 0.5f * w, 0.0f), imw);
        b.w = fminf(fmaxf(cy + 0.5f * h, 0.0f), imh);
        g_boxes[i]  = b;
        g_scores[i] = (best > 0.01f) ? best : -INFINITY;
    }
    if (tid < 64) {
        #pragma unroll
        for (int off = 16; off; off >>= 1)
            u = max(u, __shfl_xor_sync(0xffffffffu, u, off));
        if ((tid & 31) == 0) atomicMax(&g_maxu, u);
    }
}

// ---------------------------------------------------------------------------
// Kernel 2: window histogram of ordered scores, 16-ulp bins below g_maxu.
// ---------------------------------------------------------------------------
__global__ void hist_kernel(int N) {
    int gid = blockIdx.x * blockDim.x + threadIdx.x;
    if (gid >= N) return;
    unsigned u = ordf(g_scores[gid]);
    if (u > LOU) {
        unsigned bin = (g_maxu - u) >> WSHIFT;
        if (bin < WBINS) atomicAdd(&g_hist[bin], 1);
    }
}

// ---------------------------------------------------------------------------
// Kernel 3: single 1024-thread block. Inclusive scan over bins (bin 0 = top),
// find smallest B with cum >= TARGETK; publish cut score and bin starts.
// Also zeroes the histogram for the next graph replay.
// ---------------------------------------------------------------------------
__global__ void findtau_kernel() {
    __shared__ int sW[32];
    const unsigned FULL = 0xffffffffu;
    int b = threadIdx.x, lane = b & 31, wid = b >> 5;
    int v = g_hist[b];
    g_hist[b] = 0;
    int p = v;
    #pragma unroll
    for (int off = 1; off < 32; off <<= 1) {
        int t = __shfl_up_sync(FULL, p, off);
        if (lane >= off) p += t;
    }
    if (lane == 31) sW[wid] = p;
    __syncthreads();
    if (wid == 0) {
        int t = sW[lane];
        #pragma unroll
        for (int off = 1; off < 32; off <<= 1) {
            int q = __shfl_up_sync(FULL, t, off);
            if (lane >= off) t += q;
        }
        sW[lane] = t;
    }
    __syncthreads();
    int incl = p + (wid ? sW[wid - 1] : 0);
    int excl = incl - v;
    g_binStart[b] = excl;
    if ((excl < TARGETK && incl >= TARGETK) ||
        (b == WBINS - 1 && incl < TARGETK)) {
        unsigned maxu = g_maxu;
        unsigned span = ((unsigned)b << WSHIFT) + ((1u << WSHIFT) - 1u);
        g_cutU  = (maxu > LOU + 1u + span) ? (maxu - span) : (LOU + 1u);
        g_total = incl;
    }
}

// ---------------------------------------------------------------------------
// Kernel 4: compact candidates with u >= cut into bin-ordered key slots.
// ---------------------------------------------------------------------------
__global__ void compact_kernel(int N) {
    int gid = blockIdx.x * blockDim.x + threadIdx.x;
    if (gid >= N) return;
    unsigned u = ordf(g_scores[gid]);
    if (u > LOU && u >= g_cutU) {
        unsigned bin = (g_maxu - u) >> WSHIFT;
        int pos = atomicAdd(&g_binStart[bin], 1);
        if (pos < CAP)
            g_candKey[pos] = ((unsigned long long)u << 32) | (unsigned)(~gid);
    }
}

// ---------------------------------------------------------------------------
// Kernel 5: single block. Bitonic sort (desc), mask-based warp-batched greedy
// NMS (exact), class argmax of winners, output. Exact fallback retained.
// ---------------------------------------------------------------------------
__global__ void nms_kernel(float* __restrict__ out,
                           const float* __restrict__ cls,
                           int N, int C) {
    __shared__ unsigned long long sKeys[TMAX];
    __shared__ float4 sSelBox[MAXDET];
    __shared__ int    sSelIdx[MAXDET];
    __shared__ float  sSelScore[MAXDET];
    __shared__ float4 sBatch[32];
    __shared__ int    sNsel, sSup;
    __shared__ float4 sBx;
    __shared__ unsigned long long sWarp[16];
    __shared__ unsigned long long sTileP[3];

    int tid  = threadIdx.x;
    int wid  = tid >> 5;
    int lane = tid & 31;
    const unsigned FULL = 0xffffffffu;

    if (tid == 0) { sNsel = 0; g_maxu = 0u; }   // reset maxu for next replay

    int total = g_total;
    unsigned cutU = g_cutU;
    bool ovf = total > CAP;
    int cnt  = ovf ? 0 : total;

    int M = 1; while (M < cnt) M <<= 1;
    if (M < 2) M = 2;

    for (int k = tid; k < M; k += NMS_T)
        sKeys[k] = (k < cnt) ? g_candKey[k] : 0ull;
    __syncthreads();

    // ---- bitonic sort, descending ----
    if (cnt > 1) {
        for (int k2 = 2; k2 <= M; k2 <<= 1) {
            for (int j = k2 >> 1; j > 0; j >>= 1) {
                for (int i = tid; i < M; i += NMS_T) {
                    int l = i ^ j;
                    if (l > i) {
                        unsigned long long a = sKeys[i], b = sKeys[l];
                        bool desc = ((i & k2) == 0);
                        if (desc ? (a < b) : (a > b)) { sKeys[i] = b; sKeys[l] = a; }
                    }
                }
                __syncthreads();
            }
        }
    }

    // ---- warp-batched greedy NMS with suppression bitmasks (warp 0) ----
    if (tid < 32) {
        int nsel = 0;
        for (int bse = 0; bse < cnt && nsel < MAXDET; bse += 32) {
            int p = bse + tid;
            bool valid = p < cnt;
            unsigned long long key = valid ? sKeys[p] : 0ull;
            unsigned hi = (unsigned)(key >> 32);
            int   idx = (int)(~(unsigned)(key & 0xffffffffu));
            float sc  = unordf(hi);
            bool alive = valid && hi > 0x007FFFFFu;
            float4 b = alive ? g_boxes[idx]
                             : make_float4(-1e30f, -1e30f, -1e30f, -1e30f);
            sBatch[tid] = b;
            __syncwarp();

            // cull vs previously selected
            for (int j = 0; j < nsel; j++)
                if (alive && iou_gt_half(b, sSelBox[j])) alive = false;

            // 32x32 intra-batch suppression matrix (bit j: iou(me, j) > 0.5)
            unsigned supmask = 0;
            #pragma unroll 4
            for (int j = 0; j < 32; j++)
                supmask |= ((unsigned)iou_gt_half(b, sBatch[j])) << j;

            unsigned am = __ballot_sync(FULL, alive);
            unsigned selM = 0;
            while (am && nsel < MAXDET) {
                int l = __ffs(am) - 1;
                selM |= 1u << l;
                nsel++;
                if (tid == l) alive = false;
                else if (tid > l && ((supmask >> l) & 1u)) alive = false;
                am = __ballot_sync(FULL, alive);
            }
            int base = nsel - __popc(selM);
            if ((selM >> tid) & 1u) {
                int r = base + __popc(selM & ((1u << tid) - 1u));
                sSelBox[r] = b; sSelIdx[r] = idx; sSelScore[r] = sc;
            }
            __syncwarp();
        }
        if (tid == 0) sNsel = nsel;
    }
    __syncthreads();
    int nsel = sNsel;

    // ---- exact fallback (adversarial distributions only) ----
    if (nsel < MAXDET && (ovf || cutU > LOU + 1u)) {
        unsigned tauOrd = ovf ? 0xFFFFFFFFu : cutU;
        int T = (N + TILE - 1) / TILE;
        for (int t = tid; t < TMAX; t += NMS_T) {
            unsigned long long best = 0ull;
            if (t < T) {
                int bb = t * TILE;
                for (int k = 0; k < TILE; k++) {
                    int ii = bb + k;
                    if (ii >= N) break;
                    unsigned u = ordf(g_scores[ii]);
                    if (u >= tauOrd) continue;
                    unsigned long long kk =
                        ((unsigned long long)u << 32) | (unsigned)(~ii);
                    if (kk > best) best = kk;
                }
            }
            sKeys[t] = best;
        }
        __syncthreads();

        while (nsel < MAXDET) {
            unsigned long long best = 0ull;
            #pragma unroll
            for (int k = 0; k < TMAX / NMS_T; k++) {
                unsigned long long v = sKeys[tid + k * NMS_T];
                best = (v > best) ? v : best;
            }
            #pragma unroll
            for (int off = 16; off; off >>= 1) {
                unsigned long long o = __shfl_down_sync(FULL, best, off);
                best = (o > best) ? o : best;
            }
            if (lane == 0) sWarp[wid] = best;
            __syncthreads();
            if (tid < 32) {
                unsigned long long v = (tid < 16) ? sWarp[tid] : 0ull;
                #pragma unroll
                for (int off = 8; off; off >>= 1) {
                    unsigned long long o = __shfl_down_sync(FULL, v, off);
                    v = (o > v) ? o : v;
                }
                if (tid == 0) sWarp[0] = v;
            }
            __syncthreads();
            unsigned long long win = sWarp[0];
            unsigned hi = (unsigned)(win >> 32);
            if (hi <= 0x007FFFFFu) break;
            int   i   = (int)(~(unsigned)(win & 0xffffffffu));
            float val = unordf(hi);
            if (tid == 0) { g_scores[i] = -INFINITY; sBx = g_boxes[i]; sSup = 0; }
            __syncthreads();
            int t = i / TILE;
            if (tid < TILE) {
                int ii = t * TILE + tid;
                unsigned u = (ii < N) ? ordf(g_scores[ii]) : 0x007FFFFFu;
                unsigned long long kk = 0ull;
                if (u < tauOrd)
                    kk = ((unsigned long long)u << 32) | (unsigned)(~ii);
                #pragma unroll
                for (int off = 16; off; off >>= 1) {
                    unsigned long long o = __shfl_down_sync(FULL, kk, off);
                    kk = (o > kk) ? o : kk;
                }
                if (lane == 0) sTileP[wid] = kk;
            }
            if (tid >= 128 && tid < 128 + nsel) {
                if (iou_gt_half(sSelBox[tid - 128], sBx)) sSup = 1;
            }
            __syncthreads();
            if (tid == 0) {
                unsigned long long kk = sTileP[0];
                if (sTileP[1] > kk) kk = sTileP[1];
                if (sTileP[2] > kk) kk = sTileP[2];
                sKeys[t] = kk;
                if (!sSup) {
                    sSelBox[nsel] = sBx; sSelIdx[nsel] = i; sSelScore[nsel] = val;
                    sNsel = nsel + 1;
                }
            }
            __syncthreads();
            nsel = sNsel;
        }
    }
    __syncthreads();
    nsel = sNsel;

    // ---- class argmax for selected rows (warp per row) ----
    for (int r = wid; r < nsel; r += NMS_T / 32) {
        int i = sSelIdx[r];
        const float* row = cls + (long long)i * C;
        float best = -INFINITY;
        int   bidx = 0x7fffffff;
        for (int j = lane; j < C; j += 32) {
            float v = row[j];
            if (v > best) { best = v; bidx = j; }
        }
        #pragma unroll
        for (int off = 16; off; off >>= 1) {
            float ov = __shfl_down_sync(FULL, best, off);
            int   oi = __shfl_down_sync(FULL, bidx, off);
            if (ov > best || (ov == best && oi < bidx)) { best = ov; bidx = oi; }
        }
        if (lane == 0) out[100 + r] = (float)bidx;
    }

    for (int r = tid; r < MAXDET; r += NMS_T) {
        bool k = r < nsel;
        out[r]       = k ? sSelScore[r] : 0.0f;
        out[600 + r] = k ? 1.0f : 0.0f;
        float4 b = k ? sSelBox[r] : make_float4(0.f, 0.f, 0.f, 0.f);
        out[200 + 4 * r + 0] = b.x;
        out[200 + 4 * r + 1] = b.y;
        out[200 + 4 * r + 2] = b.z;
        out[200 + 4 * r + 3] = b.w;
        if (!k) out[100 + r] = -1.0f;
    }
}

extern "C" void kernel_launch(void* const* d_in, const int* in_sizes, int n_in,
                              void* d_out, int out_size) {
    const float* cls = (const float*)d_in[0];
    const float* reg = (const float*)d_in[1];
    const float* anc = (const float*)d_in[2];
    const void*  ph  = d_in[3];
    const void*  pw  = d_in[4];

    int N = in_sizes[2] / 4;
    int C = in_sizes[0] / N;

    int blocksD = (N + 63) / 64;
    decode_kernel<<<blocksD, 256>>>(cls, reg, anc, ph, pw, N, C);

    int blocksN = (N + 255) / 256;
    hist_kernel<<<blocksN, 256>>>(N);

    findtau_kernel<<<1, WBINS>>>();

    compact_kernel<<<blocksN, 256>>>(N);

    nms_kernel<<<1, NMS_T>>>((float*)d_out, cls, N, C);
}